// round 12
// baseline (speedup 1.0000x reference)
#include <cuda_runtime.h>
#include <cuda_fp16.h>
#include <cstdint>

// ---------------- problem dims ----------------
constexpr int M = 8192, N = 4096, KX = 4096, R = 16;
constexpr int KE = 4224;            // 4096 + 16 lora + 112 zero pad = 33*128

// ---------------- scratch ----------------
__device__ __align__(128) __half g_x[(size_t)M * KE];   // x (+t) as fp16
__device__ __align__(128) __half g_w[(size_t)N * KE];   // W (+2B/ws) as fp16

// ---------------- asm helpers ----------------
__device__ __forceinline__ uint32_t smem_u32(const void* p) {
    uint32_t a;
    asm("{ .reg .u64 t; cvta.to.shared.u64 t, %1; cvt.u32.u64 %0, t; }"
        : "=r"(a) : "l"(p));
    return a;
}
__device__ __forceinline__ void cp16(uint32_t dst, const void* src) {
    asm volatile("cp.async.cg.shared.global [%0], [%1], 16;" :: "r"(dst), "l"(src));
}
#define CP_COMMIT() asm volatile("cp.async.commit_group;" ::: "memory")
#define CP_WAIT1()  asm volatile("cp.async.wait_group 1;" ::: "memory")
#define LDM4(rr, addr) \
    asm volatile("ldmatrix.sync.aligned.m8n8.x4.shared.b16 {%0,%1,%2,%3}, [%4];" \
        : "=r"((rr)[0]), "=r"((rr)[1]), "=r"((rr)[2]), "=r"((rr)[3]) : "r"(addr))
#define MMA_F16(d, a, b) \
    asm volatile("mma.sync.aligned.m16n8k16.row.col.f32.f16.f16.f32 " \
        "{%0,%1,%2,%3}, {%4,%5,%6,%7}, {%8,%9}, {%0,%1,%2,%3};" \
        : "+f"((d)[0]), "+f"((d)[1]), "+f"((d)[2]), "+f"((d)[3]) \
        : "r"((a)[0]), "r"((a)[1]), "r"((a)[2]), "r"((a)[3]), \
          "r"((b)[0]), "r"((b)[1]))

// ============================================================
// Prep 1 (fused): x fp32 -> fp16 plane AND t = x @ A^T -> lora cols.
// Block = 256 threads handles 32 rows of x; A chunk staged in smem.
// Reads x exactly once.
// ============================================================
__global__ void __launch_bounds__(256)
prep_x_kernel(const float* __restrict__ x, const float* __restrict__ A) {
    __shared__ float A_s[R * 512];       // 32 KB
    const int tid = threadIdx.x;
    const int row = tid >> 3;            // 0..31
    const int l8  = tid & 7;             // 0..7
    const int m   = blockIdx.x * 32 + row;
    float acc[R];
#pragma unroll
    for (int r = 0; r < R; r++) acc[r] = 0.f;

    for (int kc = 0; kc < KX; kc += 512) {
        __syncthreads();
        for (int i = tid; i < 2048; i += 256) {
            int rr = i >> 7, cc = i & 127;
            reinterpret_cast<float4*>(A_s)[i] =
                reinterpret_cast<const float4*>(A + (size_t)rr * KX + kc)[cc];
        }
        __syncthreads();
        const float* xr = x + (size_t)m * KX + kc;
        __half* xo = g_x + (size_t)m * KE + kc;
        for (int k = l8 * 4; k < 512; k += 32) {
            float4 xv = *reinterpret_cast<const float4*>(xr + k);
            // convert + store fp16
            *reinterpret_cast<__half2*>(xo + k)     = __floats2half2_rn(xv.x, xv.y);
            *reinterpret_cast<__half2*>(xo + k + 2) = __floats2half2_rn(xv.z, xv.w);
            // accumulate t
#pragma unroll
            for (int r = 0; r < R; r++) {
                const float* Ar = A_s + r * 512 + k;
                acc[r] += xv.x * Ar[0] + xv.y * Ar[1] + xv.z * Ar[2] + xv.w * Ar[3];
            }
        }
    }
    // zero tail cols: lane l8 covers [KX + l8*16, KX + l8*16 + 16)  (8*16 = 128 = KE-KX)
    {
        __half* tail = g_x + (size_t)m * KE + KX + l8 * 16;
        uint4 z = make_uint4(0, 0, 0, 0);
        *reinterpret_cast<uint4*>(tail)     = z;
        *reinterpret_cast<uint4*>(tail + 8) = z;
    }
    // reduce t over the 8 lanes, lane 0 overwrites lora cols [KX, KX+16)
#pragma unroll
    for (int r = 0; r < R; r++) {
        float v = acc[r];
        v += __shfl_xor_sync(0xffffffffu, v, 1);
        v += __shfl_xor_sync(0xffffffffu, v, 2);
        v += __shfl_xor_sync(0xffffffffu, v, 4);
        if (l8 == 0) g_x[(size_t)m * KE + KX + r] = __float2half_rn(v);
    }
}

// ============================================================
// Prep 2: W int32 -> fp16 exact; cols [4096,4112) = (2/ws)*lB; pad zero
// ============================================================
__global__ void conv_w_kernel(const int* __restrict__ wq,
                              const float* __restrict__ ws,
                              const float* __restrict__ lB) {
    int i = blockIdx.x * blockDim.x + threadIdx.x;
    const int KQ = KE / 4;               // 1056
    if (i >= N * KQ) return;
    int row = i / KQ;
    int col = (i - row * KQ) * 4;
    __half2 o0, o1;
    if (col < KX) {
        int4 v = *reinterpret_cast<const int4*>(wq + (size_t)row * KX + col);
        o0 = __floats2half2_rn((float)v.x, (float)v.y);
        o1 = __floats2half2_rn((float)v.z, (float)v.w);
    } else if (col < KX + R) {
        float inv2 = 2.0f / ws[0];
        const float* b = lB + (size_t)row * R + (col - KX);
        o0 = __floats2half2_rn(inv2 * b[0], inv2 * b[1]);
        o1 = __floats2half2_rn(inv2 * b[2], inv2 * b[3]);
    } else {
        o0 = o1 = __floats2half2_rn(0.f, 0.f);
    }
    size_t o = (size_t)row * KE + col;
    *reinterpret_cast<__half2*>(g_w + o)     = o0;
    *reinterpret_cast<__half2*>(g_w + o + 2) = o1;
}

// ============================================================
// Main GEMM (HMMA fp16): out = ws * (x_ext @ W_ext^T)
// 128x128 CTA tile, 512 threads (16 warps, 4x4, warp 32x32),
// KS=128, 3-stage cp.async pipeline (wait_group 1).
// Small warp tile -> ~80 regs -> ptxas pipelines fragment loads.
// ============================================================
constexpr int BM = 128, BN = 128;
constexpr int KS = 128;                 // 256 B/row fp16
constexpr int PS = 3;
constexpr int NCHUNK = KE / KS;         // 33
constexpr int ROWB = 272;               // 256 data + 16 pad
constexpr int A_ST = BM * ROWB;         // 34816
constexpr int B_ST = BN * ROWB;         // 34816
constexpr int STAGE = A_ST + B_ST;      // 69632
constexpr int SMEM_GEMM = PS * STAGE;   // 208896 (<227KB, 1 CTA/SM)

__global__ void __launch_bounds__(512, 1)
gemm_kernel(const float* __restrict__ ws, float* __restrict__ out) {
    extern __shared__ __align__(128) char smem[];
    const uint32_t sb = smem_u32(smem);
    const int tid  = threadIdx.x;
    const int lane = tid & 31;
    const int wid  = tid >> 5;
    const int wm   = wid >> 2;          // 0..3 -> rows wm*32
    const int wn   = wid & 3;           // 0..3 -> cols wn*32
    const int m0 = blockIdx.y * BM;
    const int n0 = blockIdx.x * BN;

    // cp.async: row = tid>>4 (0..31), seg = (tid&15)*16B in 256B row; 4 row-groups each
    const int r0 = tid >> 4;
    const int c0 = (tid & 15) * 16;
    const uint32_t da = (uint32_t)(r0 * ROWB + c0);
    const __half* pa = g_x + (size_t)(m0 + r0) * KE + c0 / 2;
    const __half* pb = g_w + (size_t)(n0 + r0) * KE + c0 / 2;
    const size_t rstep = (size_t)32 * KE;

    // ldmatrix lane offsets
    const int arow = wm * 32 + (lane & 15);
    const uint32_t aoff = (uint32_t)(arow * ROWB) + ((lane >> 4) * 16);
    const int brow = wn * 32 + (lane & 7) + ((lane >> 4) * 8);
    const uint32_t boff = (uint32_t)(brow * ROWB) + (((lane >> 3) & 1) * 16);

    float acc[2][4][4] = {};

    // prologue: stages 0,1 <- chunks 0,1
#pragma unroll
    for (int s = 0; s < 2; s++) {
        const uint32_t st = sb + s * STAGE;
        const __half* qa = pa + (size_t)s * KS;
        const __half* qb = pb + (size_t)s * KS;
#pragma unroll
        for (int i = 0; i < 4; i++) {
            cp16(st + da + i * (32 * ROWB), qa + i * rstep);
            cp16(st + A_ST + da + i * (32 * ROWB), qb + i * rstep);
        }
        CP_COMMIT();
    }

    for (int j = 0; j < NCHUNK; j++) {
        CP_WAIT1();                       // chunk j resident; j+1 in flight
        __syncthreads();
        if (j + 2 < NCHUNK) {             // refill stage (j+2)%3 with chunk j+2
            const uint32_t st = sb + ((j + 2) % PS) * STAGE;
            const __half* qa = pa + (size_t)(j + 2) * KS;
            const __half* qb = pb + (size_t)(j + 2) * KS;
#pragma unroll
            for (int i = 0; i < 4; i++) {
                cp16(st + da + i * (32 * ROWB), qa + i * rstep);
                cp16(st + A_ST + da + i * (32 * ROWB), qb + i * rstep);
            }
        }
        CP_COMMIT();

        const uint32_t sa  = sb + (j % PS) * STAGE;
        const uint32_t sbp = sa + A_ST;
#pragma unroll
        for (int c = 0; c < 8; c++) {       // eight k16 steps per chunk
            uint32_t af[2][4], bf[4][2];
#pragma unroll
            for (int mi = 0; mi < 2; mi++)
                LDM4(af[mi], sa + aoff + mi * (16 * ROWB) + c * 32);
#pragma unroll
            for (int jj = 0; jj < 2; jj++) {
                uint32_t r[4];
                LDM4(r, sbp + boff + jj * (16 * ROWB) + c * 32);
                bf[2 * jj][0]     = r[0];  bf[2 * jj][1]     = r[1];
                bf[2 * jj + 1][0] = r[2];  bf[2 * jj + 1][1] = r[3];
            }
#pragma unroll
            for (int mi = 0; mi < 2; mi++)
#pragma unroll
                for (int nj = 0; nj < 4; nj++)
                    MMA_F16(acc[mi][nj], af[mi], bf[nj]);
        }
    }

    // epilogue: scale by ws, store (lora folded into K)
    const float sc = ws[0];
    const int quad = lane >> 2, qi = lane & 3;
#pragma unroll
    for (int mi = 0; mi < 2; mi++) {
        const int r = m0 + wm * 32 + mi * 16 + quad;
#pragma unroll
        for (int nj = 0; nj < 4; nj++) {
            const int cc = n0 + wn * 32 + nj * 8 + 2 * qi;
            float2 v0, v1;
            v0.x = sc * acc[mi][nj][0];
            v0.y = sc * acc[mi][nj][1];
            v1.x = sc * acc[mi][nj][2];
            v1.y = sc * acc[mi][nj][3];
            *reinterpret_cast<float2*>(out + (size_t)r * N + cc) = v0;
            *reinterpret_cast<float2*>(out + (size_t)(r + 8) * N + cc) = v1;
        }
    }
}

// ============================================================
// launch
// ============================================================
extern "C" void kernel_launch(void* const* d_in, const int* in_sizes, int n_in,
                              void* d_out, int out_size) {
    const float* x  = (const float*)d_in[0];
    const int*   wq = (const int*)d_in[1];
    const float* ws = (const float*)d_in[2];
    const float* lA = (const float*)d_in[3];
    const float* lB = (const float*)d_in[4];
    float* out = (float*)d_out;

    prep_x_kernel<<<M / 32, 256>>>(x, lA);
    conv_w_kernel<<<(N * (KE / 4) + 255) / 256, 256>>>(wq, ws, lB);

    cudaFuncSetAttribute(gemm_kernel,
                         cudaFuncAttributeMaxDynamicSharedMemorySize, SMEM_GEMM);
    dim3 grid(N / BN, M / BM);   // 32 x 64
    gemm_kernel<<<grid, 512, SMEM_GEMM>>>(ws, out);
}

// round 13
// speedup vs baseline: 1.2204x; 1.2204x over previous
#include <cuda_runtime.h>
#include <cuda_fp16.h>
#include <cstdint>

// ---------------- problem dims ----------------
constexpr int M = 8192, N = 4096, KX = 4096, R = 16;
constexpr int KE = 4224;            // 4096 + 16 lora + 112 zero pad = 33*128

// ---------------- scratch ----------------
__device__ __align__(128) __half g_x[(size_t)M * KE];   // x (+t) as fp16
__device__ __align__(128) __half g_w[(size_t)N * KE];   // W (+2B/ws) as fp16

// ---------------- asm helpers ----------------
__device__ __forceinline__ uint32_t smem_u32(const void* p) {
    uint32_t a;
    asm("{ .reg .u64 t; cvta.to.shared.u64 t, %1; cvt.u32.u64 %0, t; }"
        : "=r"(a) : "l"(p));
    return a;
}
__device__ __forceinline__ void cp16(uint32_t dst, const void* src) {
    asm volatile("cp.async.cg.shared.global [%0], [%1], 16;" :: "r"(dst), "l"(src));
}
#define CP_COMMIT() asm volatile("cp.async.commit_group;" ::: "memory")
#define CP_WAIT0()  asm volatile("cp.async.wait_group 0;" ::: "memory")
#define LDM4(rr, addr) \
    asm volatile("ldmatrix.sync.aligned.m8n8.x4.shared.b16 {%0,%1,%2,%3}, [%4];" \
        : "=r"((rr)[0]), "=r"((rr)[1]), "=r"((rr)[2]), "=r"((rr)[3]) : "r"(addr))
#define MMA_F16(d, a, b) \
    asm volatile("mma.sync.aligned.m16n8k16.row.col.f32.f16.f16.f32 " \
        "{%0,%1,%2,%3}, {%4,%5,%6,%7}, {%8,%9}, {%0,%1,%2,%3};" \
        : "+f"((d)[0]), "+f"((d)[1]), "+f"((d)[2]), "+f"((d)[3]) \
        : "r"((a)[0]), "r"((a)[1]), "r"((a)[2]), "r"((a)[3]), \
          "r"((b)[0]), "r"((b)[1]))

// ============================================================
// Prep 1 (fused): x fp32 -> fp16 plane AND t = x @ A^T -> lora cols.
// 256 threads handle 16 rows (16 lanes per row) -> grid 512, better occ.
// ============================================================
__global__ void __launch_bounds__(256)
prep_x_kernel(const float* __restrict__ x, const float* __restrict__ A) {
    __shared__ float A_s[R * 512];       // 32 KB
    const int tid = threadIdx.x;
    const int row = tid >> 4;            // 0..15
    const int l16 = tid & 15;            // 0..15
    const int m   = blockIdx.x * 16 + row;
    float acc[R];
#pragma unroll
    for (int r = 0; r < R; r++) acc[r] = 0.f;

    for (int kc = 0; kc < KX; kc += 512) {
        __syncthreads();
        for (int i = tid; i < 2048; i += 256) {
            int rr = i >> 7, cc = i & 127;
            reinterpret_cast<float4*>(A_s)[i] =
                reinterpret_cast<const float4*>(A + (size_t)rr * KX + kc)[cc];
        }
        __syncthreads();
        const float* xr = x + (size_t)m * KX + kc;
        __half* xo = g_x + (size_t)m * KE + kc;
        for (int k = l16 * 4; k < 512; k += 64) {
            float4 xv = *reinterpret_cast<const float4*>(xr + k);
            *reinterpret_cast<__half2*>(xo + k)     = __floats2half2_rn(xv.x, xv.y);
            *reinterpret_cast<__half2*>(xo + k + 2) = __floats2half2_rn(xv.z, xv.w);
#pragma unroll
            for (int r = 0; r < R; r++) {
                const float* Ar = A_s + r * 512 + k;
                acc[r] += xv.x * Ar[0] + xv.y * Ar[1] + xv.z * Ar[2] + xv.w * Ar[3];
            }
        }
    }
    // zero tail cols: lane l16 covers 8 halfs -> 16*8 = 128 = KE-KX
    {
        __half* tail = g_x + (size_t)m * KE + KX + l16 * 8;
        *reinterpret_cast<uint4*>(tail) = make_uint4(0, 0, 0, 0);
    }
    // reduce t over the 16 lanes, lane 0 overwrites lora cols [KX, KX+16)
#pragma unroll
    for (int r = 0; r < R; r++) {
        float v = acc[r];
        v += __shfl_xor_sync(0xffffffffu, v, 1);
        v += __shfl_xor_sync(0xffffffffu, v, 2);
        v += __shfl_xor_sync(0xffffffffu, v, 4);
        v += __shfl_xor_sync(0xffffffffu, v, 8);
        if (l16 == 0) g_x[(size_t)m * KE + KX + r] = __float2half_rn(v);
    }
}

// ============================================================
// Prep 2: W int32 -> fp16 exact; cols [4096,4112) = (2/ws)*lB; pad zero
// ============================================================
__global__ void conv_w_kernel(const int* __restrict__ wq,
                              const float* __restrict__ ws,
                              const float* __restrict__ lB) {
    int i = blockIdx.x * blockDim.x + threadIdx.x;
    const int KQ = KE / 4;               // 1056
    if (i >= N * KQ) return;
    int row = i / KQ;
    int col = (i - row * KQ) * 4;
    __half2 o0, o1;
    if (col < KX) {
        int4 v = *reinterpret_cast<const int4*>(wq + (size_t)row * KX + col);
        o0 = __floats2half2_rn((float)v.x, (float)v.y);
        o1 = __floats2half2_rn((float)v.z, (float)v.w);
    } else if (col < KX + R) {
        float inv2 = 2.0f / ws[0];
        const float* b = lB + (size_t)row * R + (col - KX);
        o0 = __floats2half2_rn(inv2 * b[0], inv2 * b[1]);
        o1 = __floats2half2_rn(inv2 * b[2], inv2 * b[3]);
    } else {
        o0 = o1 = __floats2half2_rn(0.f, 0.f);
    }
    size_t o = (size_t)row * KE + col;
    *reinterpret_cast<__half2*>(g_w + o)     = o0;
    *reinterpret_cast<__half2*>(g_w + o + 2) = o1;
}

// ============================================================
// Main GEMM (HMMA fp16): out = ws * (x_ext @ W_ext^T)
// 256x128 CTA tile, 256 threads (8 warps, 4x2, warp 64x64),
// KS=128, 2-stage cp.async pipeline (R9 schedule).
// Warp 64x64 -> 0.25 LDSM.x4 per MMA (was 0.375): smem crossbar unbound.
// ============================================================
constexpr int BM = 256, BN = 128;
constexpr int KS = 128;                 // 256 B/row fp16
constexpr int PS = 2;
constexpr int NCHUNK = KE / KS;         // 33
constexpr int ROWB = 272;               // 256 data + 16 pad
constexpr int A_ST = BM * ROWB;         // 69632
constexpr int B_ST = BN * ROWB;         // 34816
constexpr int STAGE = A_ST + B_ST;      // 104448
constexpr int SMEM_GEMM = PS * STAGE;   // 208896 (<227KB, 1 CTA/SM)

__global__ void __launch_bounds__(256, 1)
gemm_kernel(const float* __restrict__ ws, float* __restrict__ out) {
    extern __shared__ __align__(128) char smem[];
    const uint32_t sb = smem_u32(smem);
    const int tid  = threadIdx.x;
    const int lane = tid & 31;
    const int wid  = tid >> 5;
    const int wm   = wid >> 1;          // 0..3 -> rows wm*64
    const int wn   = wid & 1;           // 0..1 -> cols wn*64
    const int m0 = blockIdx.y * BM;
    const int n0 = blockIdx.x * BN;

    // cp.async: row = tid>>4 (0..15), seg = (tid&15)*16B within 256B row
    const int r0 = tid >> 4;
    const int c0 = (tid & 15) * 16;
    const uint32_t da = (uint32_t)(r0 * ROWB + c0);
    const __half* pa = g_x + (size_t)(m0 + r0) * KE + c0 / 2;
    const __half* pb = g_w + (size_t)(n0 + r0) * KE + c0 / 2;
    const size_t rstep = (size_t)16 * KE;            // 16 rows forward

    // ldmatrix lane offsets
    const int arow = wm * 64 + (lane & 15);
    const uint32_t aoff = (uint32_t)(arow * ROWB) + ((lane >> 4) * 16);
    const int brow = wn * 64 + (lane & 7) + ((lane >> 4) * 8);
    const uint32_t boff = (uint32_t)(brow * ROWB) + (((lane >> 3) & 1) * 16);

    float acc[4][8][4] = {};

    // prologue: stage 0 <- chunk 0
    {
        const uint32_t st = sb;
#pragma unroll
        for (int i = 0; i < 16; i++)                 // A: 256 rows, 16/pass
            cp16(st + da + i * (16 * ROWB), pa + i * rstep);
#pragma unroll
        for (int i = 0; i < 8; i++)                  // B: 128 rows
            cp16(st + A_ST + da + i * (16 * ROWB), pb + i * rstep);
        CP_COMMIT();
    }

    for (int j = 0; j < NCHUNK; j++) {
        CP_WAIT0();                       // chunk j resident
        __syncthreads();                  // all reads of chunk j-1 done too
        if (j + 1 < NCHUNK) {             // refill other stage with chunk j+1
            const uint32_t st = sb + ((j + 1) & 1) * STAGE;
            const __half* qa = pa + (size_t)(j + 1) * KS;
            const __half* qb = pb + (size_t)(j + 1) * KS;
#pragma unroll
            for (int i = 0; i < 16; i++)
                cp16(st + da + i * (16 * ROWB), qa + i * rstep);
#pragma unroll
            for (int i = 0; i < 8; i++)
                cp16(st + A_ST + da + i * (16 * ROWB), qb + i * rstep);
        }
        CP_COMMIT();

        const uint32_t sa  = sb + (j & 1) * STAGE;
        const uint32_t sbp = sa + A_ST;
#pragma unroll
        for (int c = 0; c < 8; c++) {       // eight k16 steps per chunk
            uint32_t af[4][4], bf[8][2];
#pragma unroll
            for (int mi = 0; mi < 4; mi++)
                LDM4(af[mi], sa + aoff + mi * (16 * ROWB) + c * 32);
#pragma unroll
            for (int jj = 0; jj < 4; jj++) {
                uint32_t r[4];
                LDM4(r, sbp + boff + jj * (16 * ROWB) + c * 32);
                bf[2 * jj][0]     = r[0];  bf[2 * jj][1]     = r[1];
                bf[2 * jj + 1][0] = r[2];  bf[2 * jj + 1][1] = r[3];
            }
#pragma unroll
            for (int mi = 0; mi < 4; mi++)
#pragma unroll
                for (int nj = 0; nj < 8; nj++)
                    MMA_F16(acc[mi][nj], af[mi], bf[nj]);
        }
    }

    // epilogue: scale by ws, store (lora folded into K)
    const float sc = ws[0];
    const int quad = lane >> 2, qi = lane & 3;
#pragma unroll
    for (int mi = 0; mi < 4; mi++) {
        const int r = m0 + wm * 64 + mi * 16 + quad;
#pragma unroll
        for (int nj = 0; nj < 8; nj++) {
            const int cc = n0 + wn * 64 + nj * 8 + 2 * qi;
            float2 v0, v1;
            v0.x = sc * acc[mi][nj][0];
            v0.y = sc * acc[mi][nj][1];
            v1.x = sc * acc[mi][nj][2];
            v1.y = sc * acc[mi][nj][3];
            *reinterpret_cast<float2*>(out + (size_t)r * N + cc) = v0;
            *reinterpret_cast<float2*>(out + (size_t)(r + 8) * N + cc) = v1;
        }
    }
}

// ============================================================
// launch
// ============================================================
extern "C" void kernel_launch(void* const* d_in, const int* in_sizes, int n_in,
                              void* d_out, int out_size) {
    const float* x  = (const float*)d_in[0];
    const int*   wq = (const int*)d_in[1];
    const float* ws = (const float*)d_in[2];
    const float* lA = (const float*)d_in[3];
    const float* lB = (const float*)d_in[4];
    float* out = (float*)d_out;

    prep_x_kernel<<<M / 16, 256>>>(x, lA);
    conv_w_kernel<<<(N * (KE / 4) + 255) / 256, 256>>>(wq, ws, lB);

    cudaFuncSetAttribute(gemm_kernel,
                         cudaFuncAttributeMaxDynamicSharedMemorySize, SMEM_GEMM);
    dim3 grid(N / BN, M / BM);   // 32 x 32
    gemm_kernel<<<grid, 256, SMEM_GEMM>>>(ws, out);
}